// round 7
// baseline (speedup 1.0000x reference)
#include <cuda_runtime.h>
#include <math.h>

#define NN 100000
#define EE 600000

// ---------------- scratch (static device globals; no allocation) ----------------
__device__ __align__(16) float g_q[NN * 128];
__device__ __align__(16) float g_k[NN * 128];
__device__ __align__(16) float g_v[NN * 128];
__device__ __align__(16) float g_skip[NN * 128];
__device__ __align__(16) float g_denom[NN * 2];
__device__ int g_count[NN + 1];   // histogram, then exclusive offsets
__device__ int g_fill[NN];
__device__ int g_perm[EE];

// ---------------- f32x2 packed helpers ----------------
__device__ __forceinline__ unsigned long long pk2(float lo, float hi) {
    unsigned long long r;
    asm("mov.b64 %0, {%1, %2};" : "=l"(r) : "f"(lo), "f"(hi));
    return r;
}
__device__ __forceinline__ float2 upk2(unsigned long long v) {
    float2 r;
    asm("mov.b64 {%0, %1}, %2;" : "=f"(r.x), "=f"(r.y) : "l"(v));
    return r;
}
__device__ __forceinline__ void ffma2(unsigned long long& d, unsigned long long a, unsigned long long b) {
    asm("fma.rn.f32x2 %0, %1, %2, %0;" : "+l"(d) : "l"(a), "l"(b));
}

// ---------------- kernel 0: zero accumulators + sort scratch ----------------
__global__ void init_zero_kernel(float4* __restrict__ out4) {
    int i = blockIdx.x * blockDim.x + threadIdx.x;
    if (i < NN * 32) out4[i] = make_float4(0.f, 0.f, 0.f, 0.f);
    if (i < NN * 2) g_denom[i] = 0.0f;
    if (i <= NN) g_count[i] = 0;
    if (i < NN) g_fill[i] = 0;
}

// ---------------- sort kernel A: histogram of dst ----------------
__global__ void hist_kernel(const int* __restrict__ ei) {
    int e = blockIdx.x * blockDim.x + threadIdx.x;
    if (e < EE) atomicAdd(&g_count[ei[EE + e]], 1);
}

// ---------------- sort kernel B: single-block exclusive scan ----------------
__global__ __launch_bounds__(1024) void scan_kernel() {
    __shared__ int wsum[32];
    __shared__ int carry_s;
    const int tid = threadIdx.x;
    const int lane = tid & 31, wid = tid >> 5;
    if (tid == 0) carry_s = 0;
    __syncthreads();
    for (int base = 0; base < NN; base += 1024) {
        int idx = base + tid;
        int v = (idx < NN) ? g_count[idx] : 0;
        int incl = v;
#pragma unroll
        for (int o = 1; o < 32; o <<= 1) {
            int t = __shfl_up_sync(0xffffffffu, incl, o);
            if (lane >= o) incl += t;
        }
        if (lane == 31) wsum[wid] = incl;
        __syncthreads();
        if (wid == 0) {
            int s = wsum[lane];
#pragma unroll
            for (int o = 1; o < 32; o <<= 1) {
                int t = __shfl_up_sync(0xffffffffu, s, o);
                if (lane >= o) s += t;
            }
            wsum[lane] = s;
        }
        __syncthreads();
        int winc = (wid > 0) ? wsum[wid - 1] : 0;
        int excl = carry_s + winc + incl - v;
        int chunk_total = wsum[31];
        __syncthreads();
        if (idx < NN) g_count[idx] = excl;
        if (tid == 0) carry_s += chunk_total;
        __syncthreads();
    }
    if (tid == 0) g_count[NN] = carry_s;
}

// ---------------- sort kernel C: place edges into buckets ----------------
__global__ void place_kernel(const int* __restrict__ ei) {
    int e = blockIdx.x * blockDim.x + threadIdx.x;
    if (e >= EE) return;
    int d = ei[EE + e];
    int pos = g_count[d] + atomicAdd(&g_fill[d], 1);
    g_perm[pos] = e;
}

// ---------------- kernel 1: node projections q,k,v,skip (f32x2) ----------------
__global__ __launch_bounds__(512) void proj_kernel(
    const float* __restrict__ x,
    const float* __restrict__ Wq, const float* __restrict__ bq,
    const float* __restrict__ Wk, const float* __restrict__ bk,
    const float* __restrict__ Wv, const float* __restrict__ bv,
    const float* __restrict__ Ws, const float* __restrict__ bs)
{
    __shared__ __align__(16) float xs[128][64];   // [k][r]
    const int node0 = blockIdx.x * 64;
    const int tid = threadIdx.x;

    for (int i = tid; i < 2048; i += 512) {
        int c4 = i >> 6;
        int r  = i & 63;
        int node = node0 + r;
        float4 v = make_float4(0.f, 0.f, 0.f, 0.f);
        if (node < NN) v = reinterpret_cast<const float4*>(x + (size_t)node * 128)[c4];
        xs[c4 * 4 + 0][r] = v.x;
        xs[c4 * 4 + 1][r] = v.y;
        xs[c4 * 4 + 2][r] = v.z;
        xs[c4 * 4 + 3][r] = v.w;
    }
    __syncthreads();

    const int m = tid >> 7;
    const int col = tid & 127;
    const float* W; const float* b; float* outp;
    if (m == 0)      { W = Wq; b = bq; outp = g_q; }
    else if (m == 1) { W = Wk; b = bk; outp = g_k; }
    else if (m == 2) { W = Wv; b = bv; outp = g_v; }
    else             { W = Ws; b = bs; outp = g_skip; }
    const float bias = b[col];

    unsigned long long acc[32];
#pragma unroll
    for (int j = 0; j < 32; j++) acc[j] = 0ull;

#pragma unroll 4
    for (int k = 0; k < 128; k++) {
        float w = W[k * 128 + col];
        unsigned long long w2 = pk2(w, w);
        const ulonglong2* xr = reinterpret_cast<const ulonglong2*>(&xs[k][0]);
#pragma unroll
        for (int j = 0; j < 16; j++) {
            ulonglong2 a = xr[j];
            ffma2(acc[2 * j],     a.x, w2);
            ffma2(acc[2 * j + 1], a.y, w2);
        }
    }

#pragma unroll
    for (int j = 0; j < 32; j++) {
        float2 v = upk2(acc[j]);
        int n0 = node0 + 2 * j;
        if (n0 < NN)     outp[(size_t)n0 * 128 + col]       = v.x + bias;
        if (n0 + 1 < NN) outp[(size_t)(n0 + 1) * 128 + col] = v.y + bias;
    }
}

// ---------------- kernel 2: fused edge pass over DST-SORTED edges ----------------
// 512 threads = 16 warps, persistent grid. We (64KB) in smem. Groups of 8 sorted
// edges: GEMV e=attr@We packed f32x2 over edge pairs; scatter run-length
// accumulates per destination (sorted -> ~2 distinct dsts per group) and flushes
// via atomics only on dst change.
#define ATTR_STRIDE 10

__global__ __launch_bounds__(512) void edge_kernel(
    const int* __restrict__ ei,
    const float* __restrict__ tarr,
    const float* __restrict__ lastu,
    const float* __restrict__ msg,
    const float* __restrict__ wt,
    const float* __restrict__ bt,
    const float* __restrict__ We,
    float* __restrict__ out)
{
    extern __shared__ __align__(16) float sm[];
    float* We_s = sm;
    float* attr_s = sm + 16384;

    const int tid = threadIdx.x;
    for (int i = tid; i < 4096; i += 512)
        reinterpret_cast<float4*>(We_s)[i] = reinterpret_cast<const float4*>(We)[i];
    __syncthreads();

    const int warp = tid >> 5;
    const int lane = tid & 31;
    float* attr_w = attr_s + warp * (128 * ATTR_STRIDE);

    const float wt0 = wt[lane], wt1 = wt[lane + 32];
    const float bt0 = bt[lane], bt1 = bt[lane + 32];

    const long gw = (long)blockIdx.x * 16 + warp;
    const long nwarps = (long)gridDim.x * 16;

    for (long base = gw * 8; base < EE; base += nwarps * 8) {
        int myE = (int)((EE - base) < 8 ? (EE - base) : 8);

        int e_r = 0, s_r = 0, d_r = 0;
        float rel_r = 0.0f;
        if (lane < myE) {
            e_r = g_perm[base + lane];          // sorted-by-dst edge id
            s_r = ei[e_r];
            d_r = ei[EE + e_r];
            rel_r = lastu[s_r] - tarr[e_r];
        }

        // build transposed edge_attr: attr_w[k*ATTR_STRIDE + mm]
        for (int mm = 0; mm < 8; mm++) {
            if (mm >= myE) break;
            float rel = __shfl_sync(0xffffffffu, rel_r, mm);
            long e = __shfl_sync(0xffffffffu, e_r, mm);
            attr_w[lane * ATTR_STRIDE + mm]        = cosf(fmaf(rel, wt0, bt0));
            attr_w[(lane + 32) * ATTR_STRIDE + mm] = cosf(fmaf(rel, wt1, bt1));
            attr_w[(lane + 64) * ATTR_STRIDE + mm] = msg[e * 64 + lane];
            attr_w[(lane + 96) * ATTR_STRIDE + mm] = msg[e * 64 + lane + 32];
        }
        __syncwarp();

        // e = attr @ We ; lane owns cols [lane*4 .. lane*4+3]
        unsigned long long acc[4][4];
#pragma unroll
        for (int p = 0; p < 4; p++)
#pragma unroll
            for (int c = 0; c < 4; c++) acc[p][c] = 0ull;

        const float4* We4 = reinterpret_cast<const float4*>(We_s);
#pragma unroll 4
        for (int k = 0; k < 128; k++) {
            float4 w = We4[k * 32 + lane];
            unsigned long long wx = pk2(w.x, w.x);
            unsigned long long wy = pk2(w.y, w.y);
            unsigned long long wz = pk2(w.z, w.z);
            unsigned long long ww = pk2(w.w, w.w);
            const unsigned long long* ap =
                reinterpret_cast<const unsigned long long*>(attr_w + k * ATTR_STRIDE);
            unsigned long long a0 = ap[0], a1 = ap[1], a2 = ap[2], a3 = ap[3];
            ffma2(acc[0][0], a0, wx); ffma2(acc[0][1], a0, wy);
            ffma2(acc[0][2], a0, wz); ffma2(acc[0][3], a0, ww);
            ffma2(acc[1][0], a1, wx); ffma2(acc[1][1], a1, wy);
            ffma2(acc[1][2], a1, wz); ffma2(acc[1][3], a1, ww);
            ffma2(acc[2][0], a2, wx); ffma2(acc[2][1], a2, wy);
            ffma2(acc[2][2], a2, wz); ffma2(acc[2][3], a2, ww);
            ffma2(acc[3][0], a3, wx); ffma2(acc[3][1], a3, wy);
            ffma2(acc[3][2], a3, wz); ffma2(acc[3][3], a3, ww);
        }

        // attention + run-length-deduped scatter (edges sorted by dst)
        float oa0 = 0.f, oa1 = 0.f, oa2 = 0.f, oa3 = 0.f, exacc = 0.f;
        int cur_d = -1;
        float4 q4 = make_float4(0.f, 0.f, 0.f, 0.f);

        for (int mm = 0; mm < myE; mm++) {
            int s = __shfl_sync(0xffffffffu, s_r, mm);
            int d = __shfl_sync(0xffffffffu, d_r, mm);

            if (d != cur_d) {                  // uniform branch
                if (cur_d >= 0) {
                    float* op = out + (size_t)cur_d * 128 + lane * 4;
                    atomicAdd(op + 0, oa0);
                    atomicAdd(op + 1, oa1);
                    atomicAdd(op + 2, oa2);
                    atomicAdd(op + 3, oa3);
                    if (lane == 0)  atomicAdd(&g_denom[(size_t)cur_d * 2 + 0], exacc);
                    if (lane == 16) atomicAdd(&g_denom[(size_t)cur_d * 2 + 1], exacc);
                }
                oa0 = oa1 = oa2 = oa3 = 0.f;
                exacc = 0.f;
                cur_d = d;
                q4 = reinterpret_cast<const float4*>(g_q + (size_t)d * 128)[lane];
            }

            float em[4];
#pragma unroll
            for (int c = 0; c < 4; c++) {
                float2 t = upk2(acc[mm >> 1][c]);
                em[c] = (mm & 1) ? t.y : t.x;
            }

            float4 k4 = reinterpret_cast<const float4*>(g_k + (size_t)s * 128)[lane];
            float4 v4 = reinterpret_cast<const float4*>(g_v + (size_t)s * 128)[lane];

            float kj0 = k4.x + em[0];
            float kj1 = k4.y + em[1];
            float kj2 = k4.z + em[2];
            float kj3 = k4.w + em[3];

            float p = q4.x * kj0 + q4.y * kj1 + q4.z * kj2 + q4.w * kj3;
            p += __shfl_xor_sync(0xffffffffu, p, 1);
            p += __shfl_xor_sync(0xffffffffu, p, 2);
            p += __shfl_xor_sync(0xffffffffu, p, 4);
            p += __shfl_xor_sync(0xffffffffu, p, 8);

            float ex = expf(p * 0.125f);       // 1/sqrt(64)

            oa0 = fmaf(ex, v4.x + em[0], oa0);
            oa1 = fmaf(ex, v4.y + em[1], oa1);
            oa2 = fmaf(ex, v4.z + em[2], oa2);
            oa3 = fmaf(ex, v4.w + em[3], oa3);
            exacc += ex;
        }
        if (cur_d >= 0) {
            float* op = out + (size_t)cur_d * 128 + lane * 4;
            atomicAdd(op + 0, oa0);
            atomicAdd(op + 1, oa1);
            atomicAdd(op + 2, oa2);
            atomicAdd(op + 3, oa3);
            if (lane == 0)  atomicAdd(&g_denom[(size_t)cur_d * 2 + 0], exacc);
            if (lane == 16) atomicAdd(&g_denom[(size_t)cur_d * 2 + 1], exacc);
        }
        __syncwarp();
    }
}

// ---------------- kernel 3: finalize out = acc/denom + skip (float4) ----------------
__global__ void finalize_kernel(float4* __restrict__ out4) {
    int i = blockIdx.x * blockDim.x + threadIdx.x;
    if (i >= NN * 32) return;
    int n = i >> 5;
    int c4 = i & 31;
    int h = c4 >> 4;
    float inv = 1.0f / (g_denom[n * 2 + h] + 1e-16f);
    float4 o = out4[i];
    float4 s = reinterpret_cast<const float4*>(g_skip)[i];
    o.x = o.x * inv + s.x;
    o.y = o.y * inv + s.y;
    o.z = o.z * inv + s.z;
    o.w = o.w * inv + s.w;
    out4[i] = o;
}

// ---------------- launcher ----------------
extern "C" void kernel_launch(void* const* d_in, const int* in_sizes, int n_in,
                              void* d_out, int out_size)
{
    const float* x     = (const float*)d_in[0];
    const float* lastu = (const float*)d_in[1];
    const int*   ei    = (const int*)d_in[2];
    const float* tarr  = (const float*)d_in[3];
    const float* msg   = (const float*)d_in[4];
    const float* wt    = (const float*)d_in[5];
    const float* bt    = (const float*)d_in[6];
    const float* Wq    = (const float*)d_in[7];
    const float* bq    = (const float*)d_in[8];
    const float* Wk    = (const float*)d_in[9];
    const float* bk    = (const float*)d_in[10];
    const float* Wv    = (const float*)d_in[11];
    const float* bv    = (const float*)d_in[12];
    const float* We    = (const float*)d_in[13];
    const float* Ws    = (const float*)d_in[14];
    const float* bs    = (const float*)d_in[15];
    float* out = (float*)d_out;

    init_zero_kernel<<<(NN * 32 + 511) / 512, 512>>>((float4*)out);

    hist_kernel<<<(EE + 255) / 256, 256>>>(ei);
    scan_kernel<<<1, 1024>>>();
    place_kernel<<<(EE + 255) / 256, 256>>>(ei);

    proj_kernel<<<(NN + 63) / 64, 512>>>(x, Wq, bq, Wk, bk, Wv, bv, Ws, bs);

    const int smem = (16384 + 16 * 128 * ATTR_STRIDE) * sizeof(float);  // 147456 B
    cudaFuncSetAttribute(edge_kernel, cudaFuncAttributeMaxDynamicSharedMemorySize, smem);
    edge_kernel<<<148, 512, smem>>>(ei, tarr, lastu, msg, wt, bt, We, out);

    finalize_kernel<<<(NN * 32 + 255) / 256, 256>>>((float4*)out);
}

// round 11
// speedup vs baseline: 1.1104x; 1.1104x over previous
#include <cuda_runtime.h>
#include <math.h>

#define NN 100000
#define EE 600000

// ---------------- scratch (static device globals; no allocation) ----------------
__device__ __align__(16) float g_q[NN * 128];
__device__ __align__(16) float g_kv[NN * 256];    // interleaved: k row | v row
__device__ __align__(16) float g_skip[NN * 128];
__device__ __align__(16) float g_denom[NN * 2];

// ---------------- f32x2 packed helpers ----------------
__device__ __forceinline__ unsigned long long pk2(float lo, float hi) {
    unsigned long long r;
    asm("mov.b64 %0, {%1, %2};" : "=l"(r) : "f"(lo), "f"(hi));
    return r;
}
__device__ __forceinline__ float2 upk2(unsigned long long v) {
    float2 r;
    asm("mov.b64 {%0, %1}, %2;" : "=f"(r.x), "=f"(r.y) : "l"(v));
    return r;
}
__device__ __forceinline__ void ffma2(unsigned long long& d, unsigned long long a, unsigned long long b) {
    asm("fma.rn.f32x2 %0, %1, %2, %0;" : "+l"(d) : "l"(a), "l"(b));
}
// vectorized global reduction (sm_90+): one instruction for 16B
__device__ __forceinline__ void red_add_v4(float* p, float a, float b, float c, float d) {
    asm volatile("red.global.add.v4.f32 [%0], {%1, %2, %3, %4};"
                 :: "l"(p), "f"(a), "f"(b), "f"(c), "f"(d) : "memory");
}

// ---------------- kernel 0: zero accumulators ----------------
__global__ void init_zero_kernel(float4* __restrict__ out4) {
    int i = blockIdx.x * blockDim.x + threadIdx.x;
    if (i < NN * 32) out4[i] = make_float4(0.f, 0.f, 0.f, 0.f);
    if (i < NN * 2) g_denom[i] = 0.0f;
}

// ---------------- kernel 1: node projections q,k,v,skip (f32x2) ----------------
// 512 threads: m = tid>>7 selects matrix, col = tid&127. 64 nodes per block.
// x tile staged TRANSPOSED: xs[k][r] so row-pairs pack into f32x2 operands.
__global__ __launch_bounds__(512) void proj_kernel(
    const float* __restrict__ x,
    const float* __restrict__ Wq, const float* __restrict__ bq,
    const float* __restrict__ Wk, const float* __restrict__ bk,
    const float* __restrict__ Wv, const float* __restrict__ bv,
    const float* __restrict__ Ws, const float* __restrict__ bs)
{
    __shared__ __align__(16) float xs[128][64];   // [k][r]
    const int node0 = blockIdx.x * 64;
    const int tid = threadIdx.x;

    for (int i = tid; i < 2048; i += 512) {
        int c4 = i >> 6;
        int r  = i & 63;
        int node = node0 + r;
        float4 v = make_float4(0.f, 0.f, 0.f, 0.f);
        if (node < NN) v = reinterpret_cast<const float4*>(x + (size_t)node * 128)[c4];
        xs[c4 * 4 + 0][r] = v.x;
        xs[c4 * 4 + 1][r] = v.y;
        xs[c4 * 4 + 2][r] = v.z;
        xs[c4 * 4 + 3][r] = v.w;
    }
    __syncthreads();

    const int m = tid >> 7;
    const int col = tid & 127;
    const float* W; const float* b; float* outp;
    size_t rstride; int coff;
    if (m == 0)      { W = Wq; b = bq; outp = g_q;    rstride = 128; coff = 0; }
    else if (m == 1) { W = Wk; b = bk; outp = g_kv;   rstride = 256; coff = 0; }
    else if (m == 2) { W = Wv; b = bv; outp = g_kv;   rstride = 256; coff = 128; }
    else             { W = Ws; b = bs; outp = g_skip; rstride = 128; coff = 0; }
    const float bias = b[col];

    unsigned long long acc[32];   // acc[j] = rows (2j, 2j+1) for this col
#pragma unroll
    for (int j = 0; j < 32; j++) acc[j] = 0ull;

#pragma unroll 4
    for (int k = 0; k < 128; k++) {
        float w = W[k * 128 + col];
        unsigned long long w2 = pk2(w, w);
        const ulonglong2* xr = reinterpret_cast<const ulonglong2*>(&xs[k][0]);
#pragma unroll
        for (int j = 0; j < 16; j++) {
            ulonglong2 a = xr[j];
            ffma2(acc[2 * j],     a.x, w2);
            ffma2(acc[2 * j + 1], a.y, w2);
        }
    }

#pragma unroll
    for (int j = 0; j < 32; j++) {
        float2 v = upk2(acc[j]);
        int n0 = node0 + 2 * j;
        if (n0 < NN)     outp[(size_t)n0 * rstride + coff + col]       = v.x + bias;
        if (n0 + 1 < NN) outp[(size_t)(n0 + 1) * rstride + coff + col] = v.y + bias;
    }
}

// ---------------- kernel 2: fused edge pass (f32x2 GEMV, unsorted stream) ----------------
// 512 threads = 16 warps, persistent grid of 148 blocks. We (64KB) in smem.
// attr stored TRANSPOSED per warp: attr_t[k][mm], stride 10 floats per k.
// Scatter uses red.global.add.v4.f32 -> 1 LSU op per 16B instead of 4.
#define ATTR_STRIDE 10

__global__ __launch_bounds__(512) void edge_kernel(
    const int* __restrict__ ei,
    const float* __restrict__ tarr,
    const float* __restrict__ lastu,
    const float* __restrict__ msg,
    const float* __restrict__ wt,
    const float* __restrict__ bt,
    const float* __restrict__ We,
    float* __restrict__ out)
{
    extern __shared__ __align__(16) float sm[];
    float* We_s = sm;                            // 16384 floats
    float* attr_s = sm + 16384;                  // 16 warps * 128*ATTR_STRIDE

    const int tid = threadIdx.x;
    for (int i = tid; i < 4096; i += 512)
        reinterpret_cast<float4*>(We_s)[i] = reinterpret_cast<const float4*>(We)[i];
    __syncthreads();

    const int warp = tid >> 5;
    const int lane = tid & 31;
    float* attr_w = attr_s + warp * (128 * ATTR_STRIDE);

    const float wt0 = wt[lane], wt1 = wt[lane + 32];
    const float bt0 = bt[lane], bt1 = bt[lane + 32];

    const long gw = (long)blockIdx.x * 16 + warp;
    const long nwarps = (long)gridDim.x * 16;

    for (long base = gw * 8; base < EE; base += nwarps * 8) {
        int myE = (int)((EE - base) < 8 ? (EE - base) : 8);

        int s_r = 0, d_r = 0;
        float rel_r = 0.0f;
        if (lane < myE) {
            long e = base + lane;
            s_r = ei[e];
            d_r = ei[EE + e];
            rel_r = lastu[s_r] - tarr[e];
        }

        // build transposed edge_attr: attr_w[k*ATTR_STRIDE + mm]
        for (int mm = 0; mm < 8; mm++) {
            if (mm >= myE) break;
            float rel = __shfl_sync(0xffffffffu, rel_r, mm);
            long e = base + mm;
            attr_w[lane * ATTR_STRIDE + mm]        = cosf(fmaf(rel, wt0, bt0));
            attr_w[(lane + 32) * ATTR_STRIDE + mm] = cosf(fmaf(rel, wt1, bt1));
            attr_w[(lane + 64) * ATTR_STRIDE + mm] = msg[e * 64 + lane];
            attr_w[(lane + 96) * ATTR_STRIDE + mm] = msg[e * 64 + lane + 32];
        }
        __syncwarp();

        // e = attr @ We ; lane owns cols [lane*4 .. lane*4+3]
        // acc[p][c]: edge-pair (2p, 2p+1), column c -- packed f32x2 over edges
        unsigned long long acc[4][4];
#pragma unroll
        for (int p = 0; p < 4; p++)
#pragma unroll
            for (int c = 0; c < 4; c++) acc[p][c] = 0ull;

        const float4* We4 = reinterpret_cast<const float4*>(We_s);
#pragma unroll 4
        for (int k = 0; k < 128; k++) {
            float4 w = We4[k * 32 + lane];
            unsigned long long wx = pk2(w.x, w.x);
            unsigned long long wy = pk2(w.y, w.y);
            unsigned long long wz = pk2(w.z, w.z);
            unsigned long long ww = pk2(w.w, w.w);
            const unsigned long long* ap =
                reinterpret_cast<const unsigned long long*>(attr_w + k * ATTR_STRIDE);
            unsigned long long a0 = ap[0], a1 = ap[1], a2 = ap[2], a3 = ap[3];
            ffma2(acc[0][0], a0, wx); ffma2(acc[0][1], a0, wy);
            ffma2(acc[0][2], a0, wz); ffma2(acc[0][3], a0, ww);
            ffma2(acc[1][0], a1, wx); ffma2(acc[1][1], a1, wy);
            ffma2(acc[1][2], a1, wz); ffma2(acc[1][3], a1, ww);
            ffma2(acc[2][0], a2, wx); ffma2(acc[2][1], a2, wy);
            ffma2(acc[2][2], a2, wz); ffma2(acc[2][3], a2, ww);
            ffma2(acc[3][0], a3, wx); ffma2(acc[3][1], a3, wy);
            ffma2(acc[3][2], a3, wz); ffma2(acc[3][3], a3, ww);
        }

        // attention + scatter per edge
        for (int mm = 0; mm < 8; mm++) {
            if (mm >= myE) break;
            int s = __shfl_sync(0xffffffffu, s_r, mm);
            int d = __shfl_sync(0xffffffffu, d_r, mm);

            float em[4];
#pragma unroll
            for (int c = 0; c < 4; c++) {
                float2 t = upk2(acc[mm >> 1][c]);
                em[c] = (mm & 1) ? t.y : t.x;
            }

            const float* kvrow = g_kv + (size_t)s * 256;
            float4 q4 = reinterpret_cast<const float4*>(g_q + (size_t)d * 128)[lane];
            float4 k4 = reinterpret_cast<const float4*>(kvrow)[lane];
            float4 v4 = reinterpret_cast<const float4*>(kvrow + 128)[lane];

            float kj0 = k4.x + em[0];
            float kj1 = k4.y + em[1];
            float kj2 = k4.z + em[2];
            float kj3 = k4.w + em[3];

            float p = q4.x * kj0 + q4.y * kj1 + q4.z * kj2 + q4.w * kj3;
            p += __shfl_xor_sync(0xffffffffu, p, 1);
            p += __shfl_xor_sync(0xffffffffu, p, 2);
            p += __shfl_xor_sync(0xffffffffu, p, 4);
            p += __shfl_xor_sync(0xffffffffu, p, 8);

            float ex = expf(p * 0.125f);   // 1/sqrt(64)

            float o0 = ex * (v4.x + em[0]);
            float o1 = ex * (v4.y + em[1]);
            float o2 = ex * (v4.z + em[2]);
            float o3 = ex * (v4.w + em[3]);

            red_add_v4(out + (size_t)d * 128 + lane * 4, o0, o1, o2, o3);

            if (lane == 0)  atomicAdd(&g_denom[(size_t)d * 2 + 0], ex);
            if (lane == 16) atomicAdd(&g_denom[(size_t)d * 2 + 1], ex);
        }
        __syncwarp();
    }
}

// ---------------- kernel 3: finalize out = acc/denom + skip (float4) ----------------
__global__ void finalize_kernel(float4* __restrict__ out4) {
    int i = blockIdx.x * blockDim.x + threadIdx.x;
    if (i >= NN * 32) return;
    int n = i >> 5;
    int c4 = i & 31;
    int h = c4 >> 4;
    float inv = 1.0f / (g_denom[n * 2 + h] + 1e-16f);
    float4 o = out4[i];
    float4 s = reinterpret_cast<const float4*>(g_skip)[i];
    o.x = o.x * inv + s.x;
    o.y = o.y * inv + s.y;
    o.z = o.z * inv + s.z;
    o.w = o.w * inv + s.w;
    out4[i] = o;
}

// ---------------- launcher ----------------
extern "C" void kernel_launch(void* const* d_in, const int* in_sizes, int n_in,
                              void* d_out, int out_size)
{
    const float* x     = (const float*)d_in[0];
    const float* lastu = (const float*)d_in[1];
    const int*   ei    = (const int*)d_in[2];
    const float* tarr  = (const float*)d_in[3];
    const float* msg   = (const float*)d_in[4];
    const float* wt    = (const float*)d_in[5];
    const float* bt    = (const float*)d_in[6];
    const float* Wq    = (const float*)d_in[7];
    const float* bq    = (const float*)d_in[8];
    const float* Wk    = (const float*)d_in[9];
    const float* bk    = (const float*)d_in[10];
    const float* Wv    = (const float*)d_in[11];
    const float* bv    = (const float*)d_in[12];
    const float* We    = (const float*)d_in[13];
    const float* Ws    = (const float*)d_in[14];
    const float* bs    = (const float*)d_in[15];
    float* out = (float*)d_out;

    init_zero_kernel<<<(NN * 32 + 511) / 512, 512>>>((float4*)out);

    proj_kernel<<<(NN + 63) / 64, 512>>>(x, Wq, bq, Wk, bk, Wv, bv, Ws, bs);

    const int smem = (16384 + 16 * 128 * ATTR_STRIDE) * sizeof(float);  // 147456 B
    cudaFuncSetAttribute(edge_kernel, cudaFuncAttributeMaxDynamicSharedMemorySize, smem);
    edge_kernel<<<148, 512, smem>>>(ei, tarr, lastu, msg, wt, bt, We, out);

    finalize_kernel<<<(NN * 32 + 255) / 256, 256>>>((float4*)out);
}